// round 10
// baseline (speedup 1.0000x reference)
#include <cuda_runtime.h>
#include <math.h>
#include <stdint.h>

// Problem constants
#define BATCH 2
#define SEQ   2048
#define CDIM  256
#define HEADS 8
#define HDIM  32
#define TOK   4096          // tokens per stream (BATCH*SEQ)
#define TTOK  8192          // total tokens (both streams)
#define HID   1024

// qk scale: 32^-0.25 (applied to both sides in reference)
#define QK_SCALE 0.42044820762685725f

// ---------------- scratch (static device allocations) ----------------
__device__ float g_n [TTOK * CDIM];        // ln1 output
__device__ float g_qk[TTOK * CDIM];        // qk projection (scaled)
__device__ float g_v [TTOK * CDIM];        // v projection
__device__ float g_m [TTOK * CDIM];        // attention output
__device__ float g_xm[TTOK * 2 * CDIM];    // concat(x, m@merge_w^T), ld=512
__device__ float g_h1[TTOK * HID];         // fc1+gelu output
__device__ float g_h2[TTOK * CDIM];        // fc2 output

// ---------------- packed f32x2 helpers ----------------
typedef unsigned long long u64;
__device__ __forceinline__ u64 f2fma(u64 a, u64 b, u64 c) {
    u64 d; asm("fma.rn.f32x2 %0, %1, %2, %3;" : "=l"(d) : "l"(a), "l"(b), "l"(c)); return d;
}
__device__ __forceinline__ u64 f2mul(u64 a, u64 b) {
    u64 d; asm("mul.rn.f32x2 %0, %1, %2;" : "=l"(d) : "l"(a), "l"(b)); return d;
}
__device__ __forceinline__ u64 f2pack(float x) {
    u64 d; asm("mov.b64 %0, {%1, %1};" : "=l"(d) : "f"(x)); return d;
}
__device__ __forceinline__ float f2lo(u64 a) {
    float lo, hi; asm("mov.b64 {%0, %1}, %2;" : "=f"(lo), "=f"(hi) : "l"(a)); return lo;
}
__device__ __forceinline__ float f2hi(u64 a) {
    float lo, hi; asm("mov.b64 {%0, %1}, %2;" : "=f"(lo), "=f"(hi) : "l"(a)); return hi;
}

// ---------------- LayerNorm (warp per token) ----------------
__global__ void ln1_kernel(const float* __restrict__ x0, const float* __restrict__ x1,
                           const float* __restrict__ w, const float* __restrict__ b,
                           float* __restrict__ out)
{
    int gwarp = (blockIdx.x * blockDim.x + threadIdx.x) >> 5;
    int lane = threadIdx.x & 31;
    if (gwarp >= TTOK) return;
    const float* x = (gwarp < TOK) ? (x0 + (size_t)gwarp * CDIM)
                                   : (x1 + (size_t)(gwarp - TOK) * CDIM);
    float4 a = ((const float4*)x)[lane];
    float4 c = ((const float4*)x)[lane + 32];
    float sum = a.x + a.y + a.z + a.w + c.x + c.y + c.z + c.w;
    float sq  = a.x*a.x + a.y*a.y + a.z*a.z + a.w*a.w
              + c.x*c.x + c.y*c.y + c.z*c.z + c.w*c.w;
    #pragma unroll
    for (int o = 16; o; o >>= 1) {
        sum += __shfl_xor_sync(0xffffffffu, sum, o);
        sq  += __shfl_xor_sync(0xffffffffu, sq,  o);
    }
    float mean = sum * (1.0f / CDIM);
    float var  = sq * (1.0f / CDIM) - mean * mean;
    float rstd = rsqrtf(var + 1e-5f);

    float4 w0 = ((const float4*)w)[lane];
    float4 w1 = ((const float4*)w)[lane + 32];
    float4 b0 = ((const float4*)b)[lane];
    float4 b1 = ((const float4*)b)[lane + 32];
    float4 o0, o1;
    o0.x = (a.x - mean) * rstd * w0.x + b0.x;
    o0.y = (a.y - mean) * rstd * w0.y + b0.y;
    o0.z = (a.z - mean) * rstd * w0.z + b0.z;
    o0.w = (a.w - mean) * rstd * w0.w + b0.w;
    o1.x = (c.x - mean) * rstd * w1.x + b1.x;
    o1.y = (c.y - mean) * rstd * w1.y + b1.y;
    o1.z = (c.z - mean) * rstd * w1.z + b1.z;
    o1.w = (c.w - mean) * rstd * w1.w + b1.w;
    float4* op = (float4*)(out + (size_t)gwarp * CDIM);
    op[lane] = o0;
    op[lane + 32] = o1;
}

__device__ __forceinline__ float gelu_exact(float x) {
    return 0.5f * x * (1.0f + erff(x * 0.70710678118654752f));
}

// ---------------- fp32 SIMT GEMM w/ packed f32x2 (qk/v projections) ----------------
__global__ void gemm_kernel(const float* __restrict__ A, int lda,
                            const float* __restrict__ W,
                            float* __restrict__ Cc, int ldc,
                            int K, float scale)
{
    __shared__ float As[16][68];
    __shared__ float Bs[16][68];

    int tid = threadIdx.x;                 // 256 threads
    int m0 = blockIdx.y * 64;
    int n0 = blockIdx.x * 64;
    int lrow = tid >> 2;                   // 0..63
    int lk   = (tid & 3) << 2;             // 0,4,8,12
    const float* Aptr = A + (size_t)(m0 + lrow) * lda + lk;
    const float* Wptr = W + (size_t)(n0 + lrow) * K + lk;

    int ty = tid >> 4;
    int tx = tid & 15;

    u64 acc2[4][2];
    #pragma unroll
    for (int i = 0; i < 4; i++) { acc2[i][0] = 0ull; acc2[i][1] = 0ull; }

    for (int k0 = 0; k0 < K; k0 += 16) {
        float4 av = *(const float4*)(Aptr + k0);
        float4 wv = *(const float4*)(Wptr + k0);
        As[lk + 0][lrow] = av.x; As[lk + 1][lrow] = av.y;
        As[lk + 2][lrow] = av.z; As[lk + 3][lrow] = av.w;
        Bs[lk + 0][lrow] = wv.x; Bs[lk + 1][lrow] = wv.y;
        Bs[lk + 2][lrow] = wv.z; Bs[lk + 3][lrow] = wv.w;
        __syncthreads();
        #pragma unroll
        for (int kk = 0; kk < 16; kk++) {
            float4 a4 = *(const float4*)&As[kk][ty * 4];
            const u64* bp = (const u64*)&Bs[kk][tx * 4];
            u64 b0 = bp[0], b1 = bp[1];
            u64 a0 = f2pack(a4.x), a1 = f2pack(a4.y);
            u64 a2 = f2pack(a4.z), a3 = f2pack(a4.w);
            acc2[0][0] = f2fma(a0, b0, acc2[0][0]);
            acc2[0][1] = f2fma(a0, b1, acc2[0][1]);
            acc2[1][0] = f2fma(a1, b0, acc2[1][0]);
            acc2[1][1] = f2fma(a1, b1, acc2[1][1]);
            acc2[2][0] = f2fma(a2, b0, acc2[2][0]);
            acc2[2][1] = f2fma(a2, b1, acc2[2][1]);
            acc2[3][0] = f2fma(a3, b0, acc2[3][0]);
            acc2[3][1] = f2fma(a3, b1, acc2[3][1]);
        }
        __syncthreads();
    }

    u64 sp = f2pack(scale);
    #pragma unroll
    for (int i = 0; i < 4; i++) {
        int row = m0 + ty * 4 + i;
        u64 v0 = f2mul(acc2[i][0], sp);
        u64 v1 = f2mul(acc2[i][1], sp);
        float4 o;
        o.x = f2lo(v0); o.y = f2hi(v0);
        o.z = f2lo(v1); o.w = f2hi(v1);
        *(float4*)&Cc[(size_t)row * ldc + n0 + tx * 4] = o;
    }
}

// ---------------- tf32 helpers ----------------
__device__ __forceinline__ float to_tf32(float x) {
    uint32_t u; asm("cvt.rna.tf32.f32 %0, %1;" : "=r"(u) : "f"(x));
    return __uint_as_float(u);
}

__device__ __forceinline__ void mma_tf32(float* c, const float* a, const float* b) {
    asm volatile(
        "mma.sync.aligned.m16n8k8.row.col.f32.tf32.tf32.f32 "
        "{%0,%1,%2,%3}, {%4,%5,%6,%7}, {%8,%9}, {%0,%1,%2,%3};"
        : "+f"(c[0]), "+f"(c[1]), "+f"(c[2]), "+f"(c[3])
        : "r"(__float_as_uint(a[0])), "r"(__float_as_uint(a[1])),
          "r"(__float_as_uint(a[2])), "r"(__float_as_uint(a[3])),
          "r"(__float_as_uint(b[0])), "r"(__float_as_uint(b[1])));
}

// ---------------- tf32 tensor-core GEMM: C = act(A @ W^T + bias) ----------------
__global__ __launch_bounds__(256) void gemm_tf32(
    const float* __restrict__ A, int lda,
    const float* __restrict__ W,
    const float* __restrict__ bias,
    float* __restrict__ Cc, int ldc,
    int K, int act)
{
    __shared__ float As[128][36];
    __shared__ float Ws[64][36];

    int tid = threadIdx.x;
    int lane = tid & 31;
    int warp = tid >> 5;          // 0..7
    int warp_m = warp & 3;
    int warp_n = warp >> 2;
    int m0 = blockIdx.y * 128;
    int n0 = blockIdx.x * 64;

    int grp = lane >> 2;          // 0..7
    int tig = lane & 3;           // 0..3

    float acc[2][4][4];
    #pragma unroll
    for (int mt = 0; mt < 2; mt++)
        #pragma unroll
        for (int nt = 0; nt < 4; nt++)
            #pragma unroll
            for (int r = 0; r < 4; r++) acc[mt][nt][r] = 0.0f;

    for (int k0 = 0; k0 < K; k0 += 32) {
        #pragma unroll
        for (int i = 0; i < 4; i++) {
            int idx = tid + i * 256;
            int row = idx >> 3;
            int kc  = (idx & 7) << 2;
            float4 v = *(const float4*)&A[(size_t)(m0 + row) * lda + k0 + kc];
            As[row][kc + 0] = to_tf32(v.x);
            As[row][kc + 1] = to_tf32(v.y);
            As[row][kc + 2] = to_tf32(v.z);
            As[row][kc + 3] = to_tf32(v.w);
        }
        #pragma unroll
        for (int i = 0; i < 2; i++) {
            int idx = tid + i * 256;
            int row = idx >> 3;
            int kc  = (idx & 7) << 2;
            float4 v = *(const float4*)&W[(size_t)(n0 + row) * K + k0 + kc];
            Ws[row][kc + 0] = to_tf32(v.x);
            Ws[row][kc + 1] = to_tf32(v.y);
            Ws[row][kc + 2] = to_tf32(v.z);
            Ws[row][kc + 3] = to_tf32(v.w);
        }
        __syncthreads();

        #pragma unroll
        for (int ks = 0; ks < 4; ks++) {
            int kb = ks * 8;
            float a[2][4];
            #pragma unroll
            for (int mt = 0; mt < 2; mt++) {
                int rb = warp_m * 32 + mt * 16;
                a[mt][0] = As[rb + grp    ][kb + tig];
                a[mt][1] = As[rb + grp + 8][kb + tig];
                a[mt][2] = As[rb + grp    ][kb + tig + 4];
                a[mt][3] = As[rb + grp + 8][kb + tig + 4];
            }
            float b[4][2];
            #pragma unroll
            for (int nt = 0; nt < 4; nt++) {
                int nb = warp_n * 32 + nt * 8 + grp;
                b[nt][0] = Ws[nb][kb + tig];
                b[nt][1] = Ws[nb][kb + tig + 4];
            }
            #pragma unroll
            for (int mt = 0; mt < 2; mt++)
                #pragma unroll
                for (int nt = 0; nt < 4; nt++)
                    mma_tf32(acc[mt][nt], a[mt], b[nt]);
        }
        __syncthreads();
    }

    #pragma unroll
    for (int mt = 0; mt < 2; mt++) {
        #pragma unroll
        for (int nt = 0; nt < 4; nt++) {
            int r = m0 + warp_m * 32 + mt * 16 + grp;
            int c = n0 + warp_n * 32 + nt * 8 + tig * 2;
            float b0 = bias ? bias[c]     : 0.0f;
            float b1 = bias ? bias[c + 1] : 0.0f;
            float v0 = acc[mt][nt][0] + b0;
            float v1 = acc[mt][nt][1] + b1;
            float v2 = acc[mt][nt][2] + b0;
            float v3 = acc[mt][nt][3] + b1;
            if (act) { v0 = gelu_exact(v0); v1 = gelu_exact(v1);
                       v2 = gelu_exact(v2); v3 = gelu_exact(v3); }
            float2 p0 = make_float2(v0, v1);
            float2 p1 = make_float2(v2, v3);
            *(float2*)&Cc[(size_t)r * ldc + c]       = p0;
            *(float2*)&Cc[(size_t)(r + 8) * ldc + c] = p1;
        }
    }
}

// ---------------- tensor-core dual-direction flash attention (v2) ----------------
// Block: 128 q-rows, 4 warps x 32 rows (2 m-tiles each). 64-key tiles.
// Paired SMEM layouts: every B-fragment = one LDS.64; P staged as float4 A-frags.
__global__ __launch_bounds__(128, 3)
void attn_tc_kernel(const float* __restrict__ qk, const float* __restrict__ v,
                    float* __restrict__ out)
{
    // Kp[ks][tig][key] = {K[key][8ks+tig], K[key][8ks+tig+4]}  (key pad 68: tig bank-stride 8)
    __shared__ float2 Kp[4][4][68];
    // Vp[ks][tig][dim] = {V[8ks+tig][dim], V[8ks+tig+4][dim]}  (dim pad 36)
    __shared__ float2 Vp[8][4][36];
    // Pq[warp][ks][tig][grp] = A-fragment float4 (grp pad 10: tig bank-stride 8)
    __shared__ float4 Pq[4][8][4][10];

    const int combo = blockIdx.z;
    const int dir = combo >> 1, bb = combo & 1;
    const int h = blockIdx.y;
    const int q_base = dir * TOK + bb * SEQ;
    const int k_base = (dir ^ 1) * TOK + bb * SEQ;
    const int tid = threadIdx.x;
    const int warp = tid >> 5, lane = tid & 31;
    const int grp = lane >> 2, tig = lane & 3;
    const int m0 = blockIdx.x * 128 + warp * 32;

    // Q fragments for 2 m-tiles
    float qa[2][4][4];
    #pragma unroll
    for (int mt = 0; mt < 2; mt++) {
        const float* qr0 = &qk[(size_t)(q_base + m0 + mt * 16 + grp) * CDIM + h * HDIM];
        const float* qr1 = &qk[(size_t)(q_base + m0 + mt * 16 + grp + 8) * CDIM + h * HDIM];
        #pragma unroll
        for (int s = 0; s < 4; s++) {
            qa[mt][s][0] = to_tf32(qr0[8 * s + tig]);
            qa[mt][s][1] = to_tf32(qr1[8 * s + tig]);
            qa[mt][s][2] = to_tf32(qr0[8 * s + tig + 4]);
            qa[mt][s][3] = to_tf32(qr1[8 * s + tig + 4]);
        }
    }

    float o[2][4][4];
    #pragma unroll
    for (int mt = 0; mt < 2; mt++)
        #pragma unroll
        for (int nt = 0; nt < 4; nt++)
            #pragma unroll
            for (int r = 0; r < 4; r++) o[mt][nt][r] = 0.0f;
    float mrow[2][2] = {{-1e30f, -1e30f}, {-1e30f, -1e30f}};
    float lrow[2][2] = {{0.0f, 0.0f}, {0.0f, 0.0f}};

    for (int kt = 0; kt < SEQ; kt += 64) {
        // ---- load K/V tile into paired layouts ----
        #pragma unroll
        for (int i = 0; i < 4; i++) {
            int idx = tid + i * 128;          // 512 float4 slots
            int key = idx >> 3;
            int c4  = (idx & 7) << 2;         // dims c4..c4+3
            size_t goff = (size_t)(k_base + kt + key) * CDIM + h * HDIM + c4;
            float4 kv = *(const float4*)&qk[goff];
            int ksk = c4 >> 3;
            if ((c4 & 4) == 0) {
                Kp[ksk][0][key].x = to_tf32(kv.x);
                Kp[ksk][1][key].x = to_tf32(kv.y);
                Kp[ksk][2][key].x = to_tf32(kv.z);
                Kp[ksk][3][key].x = to_tf32(kv.w);
            } else {
                Kp[ksk][0][key].y = to_tf32(kv.x);
                Kp[ksk][1][key].y = to_tf32(kv.y);
                Kp[ksk][2][key].y = to_tf32(kv.z);
                Kp[ksk][3][key].y = to_tf32(kv.w);
            }
            float4 vv = *(const float4*)&v[goff];
            int ksv = key >> 3;
            int rv = key & 7;
            int tv = rv & 3;
            if (rv < 4) {
                Vp[ksv][tv][c4 + 0].x = to_tf32(vv.x);
                Vp[ksv][tv][c4 + 1].x = to_tf32(vv.y);
                Vp[ksv][tv][c4 + 2].x = to_tf32(vv.z);
                Vp[ksv][tv][c4 + 3].x = to_tf32(vv.w);
            } else {
                Vp[ksv][tv][c4 + 0].y = to_tf32(vv.x);
                Vp[ksv][tv][c4 + 1].y = to_tf32(vv.y);
                Vp[ksv][tv][c4 + 2].y = to_tf32(vv.z);
                Vp[ksv][tv][c4 + 3].y = to_tf32(vv.w);
            }
        }
        __syncthreads();

        #pragma unroll
        for (int mt = 0; mt < 2; mt++) {
            // ---- S = Q @ K^T ----
            float s[8][4];
            #pragma unroll
            for (int nt = 0; nt < 8; nt++)
                #pragma unroll
                for (int r = 0; r < 4; r++) s[nt][r] = 0.0f;
            #pragma unroll
            for (int ks = 0; ks < 4; ks++) {
                #pragma unroll
                for (int nt = 0; nt < 8; nt++) {
                    float2 kb = Kp[ks][tig][nt * 8 + grp];
                    float bfr[2] = {kb.x, kb.y};
                    mma_tf32(s[nt], qa[mt][ks], bfr);
                }
            }

            // ---- online softmax (rows grp / grp+8) ----
            float mx_lo = -1e30f, mx_hi = -1e30f;
            #pragma unroll
            for (int nt = 0; nt < 8; nt++) {
                mx_lo = fmaxf(mx_lo, fmaxf(s[nt][0], s[nt][1]));
                mx_hi = fmaxf(mx_hi, fmaxf(s[nt][2], s[nt][3]));
            }
            mx_lo = fmaxf(mx_lo, __shfl_xor_sync(0xffffffffu, mx_lo, 1));
            mx_lo = fmaxf(mx_lo, __shfl_xor_sync(0xffffffffu, mx_lo, 2));
            mx_hi = fmaxf(mx_hi, __shfl_xor_sync(0xffffffffu, mx_hi, 1));
            mx_hi = fmaxf(mx_hi, __shfl_xor_sync(0xffffffffu, mx_hi, 2));

            float mn_lo = fmaxf(mrow[mt][0], mx_lo);
            float mn_hi = fmaxf(mrow[mt][1], mx_hi);
            float corr_lo = __expf(mrow[mt][0] - mn_lo);
            float corr_hi = __expf(mrow[mt][1] - mn_hi);
            mrow[mt][0] = mn_lo; mrow[mt][1] = mn_hi;
            lrow[mt][0] *= corr_lo; lrow[mt][1] *= corr_hi;
            #pragma unroll
            for (int nt = 0; nt < 4; nt++) {
                o[mt][nt][0] *= corr_lo; o[mt][nt][1] *= corr_lo;
                o[mt][nt][2] *= corr_hi; o[mt][nt][3] *= corr_hi;
            }

            float sum_lo = 0.0f, sum_hi = 0.0f;
            #pragma unroll
            for (int nt = 0; nt < 8; nt++) {
                s[nt][0] = __expf(s[nt][0] - mn_lo);
                s[nt][1] = __expf(s[nt][1] - mn_lo);
                s[nt][2] = __expf(s[nt][2] - mn_hi);
                s[nt][3] = __expf(s[nt][3] - mn_hi);
                sum_lo += s[nt][0] + s[nt][1];
                sum_hi += s[nt][2] + s[nt][3];
            }
            sum_lo += __shfl_xor_sync(0xffffffffu, sum_lo, 1);
            sum_lo += __shfl_xor_sync(0xffffffffu, sum_lo, 2);
            sum_hi += __shfl_xor_sync(0xffffffffu, sum_hi, 1);
            sum_hi += __shfl_xor_sync(0xffffffffu, sum_hi, 2);
            lrow[mt][0] += sum_lo; lrow[mt][1] += sum_hi;

            // ---- stage P as A-fragments: two STS.64 per n-tile ----
            {
                int tp  = (2 * tig) & 3;
                int off = (tig < 2) ? 0 : 2;
                #pragma unroll
                for (int nt = 0; nt < 8; nt++) {
                    float* b0 = (float*)&Pq[warp][nt][tp][grp] + off;
                    float* b1 = (float*)&Pq[warp][nt][tp + 1][grp] + off;
                    *(float2*)b0 = make_float2(to_tf32(s[nt][0]), to_tf32(s[nt][2]));
                    *(float2*)b1 = make_float2(to_tf32(s[nt][1]), to_tf32(s[nt][3]));
                }
            }
            __syncwarp();

            // ---- O += P @ V : A = one LDS.128, B = one LDS.64 ----
            #pragma unroll
            for (int ks = 0; ks < 8; ks++) {
                float4 af = Pq[warp][ks][tig][grp];
                float a[4] = {af.x, af.y, af.z, af.w};
                #pragma unroll
                for (int nt = 0; nt < 4; nt++) {
                    float2 vb = Vp[ks][tig][nt * 8 + grp];
                    float bfr[2] = {vb.x, vb.y};
                    mma_tf32(o[mt][nt], a, bfr);
                }
            }
            __syncwarp();
        }
        __syncthreads();
    }

    // ---- normalize & write ----
    #pragma unroll
    for (int mt = 0; mt < 2; mt++) {
        float inv_lo = 1.0f / lrow[mt][0];
        float inv_hi = 1.0f / lrow[mt][1];
        float* or0 = &out[(size_t)(q_base + m0 + mt * 16 + grp) * CDIM + h * HDIM];
        float* or1 = &out[(size_t)(q_base + m0 + mt * 16 + grp + 8) * CDIM + h * HDIM];
        #pragma unroll
        for (int nt = 0; nt < 4; nt++) {
            *(float2*)&or0[nt * 8 + 2 * tig] = make_float2(o[mt][nt][0] * inv_lo, o[mt][nt][1] * inv_lo);
            *(float2*)&or1[nt * 8 + 2 * tig] = make_float2(o[mt][nt][2] * inv_hi, o[mt][nt][3] * inv_hi);
        }
    }
}

// ---------------- copy x into concat buffer (cols 0..255 of g_xm, ld=512) ----------------
__global__ void copyx_kernel(const float* __restrict__ x0, const float* __restrict__ x1,
                             float* __restrict__ xm)
{
    int idx = blockIdx.x * blockDim.x + threadIdx.x;
    if (idx >= TTOK * CDIM / 4) return;
    int tok = idx >> 6;
    int c4  = idx & 63;
    const float4* src = (const float4*)((tok < TOK) ? (x0 + (size_t)tok * CDIM)
                                                    : (x1 + (size_t)(tok - TOK) * CDIM));
    ((float4*)(xm + (size_t)tok * (2 * CDIM)))[c4] = src[c4];
}

// ---------------- final: out = x + gamma * LN(h2; ln2_w, ln2_b) ----------------
__global__ void final_kernel(const float* __restrict__ x0, const float* __restrict__ x1,
                             const float* __restrict__ h2, const float* __restrict__ gamma,
                             const float* __restrict__ w, const float* __restrict__ b,
                             float* __restrict__ out)
{
    int gwarp = (blockIdx.x * blockDim.x + threadIdx.x) >> 5;
    int lane = threadIdx.x & 31;
    if (gwarp >= TTOK) return;
    const float* x = (gwarp < TOK) ? (x0 + (size_t)gwarp * CDIM)
                                   : (x1 + (size_t)(gwarp - TOK) * CDIM);
    const float* hh = h2 + (size_t)gwarp * CDIM;

    float4 a = ((const float4*)hh)[lane];
    float4 c = ((const float4*)hh)[lane + 32];
    float sum = a.x + a.y + a.z + a.w + c.x + c.y + c.z + c.w;
    float sq  = a.x*a.x + a.y*a.y + a.z*a.z + a.w*a.w
              + c.x*c.x + c.y*c.y + c.z*c.z + c.w*c.w;
    #pragma unroll
    for (int o = 16; o; o >>= 1) {
        sum += __shfl_xor_sync(0xffffffffu, sum, o);
        sq  += __shfl_xor_sync(0xffffffffu, sq,  o);
    }
    float mean = sum * (1.0f / CDIM);
    float var  = sq * (1.0f / CDIM) - mean * mean;
    float rstd = rsqrtf(var + 1e-5f);

    float4 xa = ((const float4*)x)[lane];
    float4 xc = ((const float4*)x)[lane + 32];
    float4 w0 = ((const float4*)w)[lane];
    float4 w1 = ((const float4*)w)[lane + 32];
    float4 b0 = ((const float4*)b)[lane];
    float4 b1 = ((const float4*)b)[lane + 32];
    float4 g0 = ((const float4*)gamma)[lane];
    float4 g1 = ((const float4*)gamma)[lane + 32];

    float4 o0, o1;
    o0.x = xa.x + g0.x * ((a.x - mean) * rstd * w0.x + b0.x);
    o0.y = xa.y + g0.y * ((a.y - mean) * rstd * w0.y + b0.y);
    o0.z = xa.z + g0.z * ((a.z - mean) * rstd * w0.z + b0.z);
    o0.w = xa.w + g0.w * ((a.w - mean) * rstd * w0.w + b0.w);
    o1.x = xc.x + g1.x * ((c.x - mean) * rstd * w1.x + b1.x);
    o1.y = xc.y + g1.y * ((c.y - mean) * rstd * w1.y + b1.y);
    o1.z = xc.z + g1.z * ((c.z - mean) * rstd * w1.z + b1.z);
    o1.w = xc.w + g1.w * ((c.w - mean) * rstd * w1.w + b1.w);

    float4* op = (float4*)(out + (size_t)gwarp * CDIM);
    op[lane] = o0;
    op[lane + 32] = o1;
}

// ---------------- launch ----------------
extern "C" void kernel_launch(void* const* d_in, const int* in_sizes, int n_in,
                              void* d_out, int out_size)
{
    const float* x0      = (const float*)d_in[0];
    const float* x1      = (const float*)d_in[1];
    const float* qk_w    = (const float*)d_in[2];
    const float* v_w     = (const float*)d_in[3];
    const float* merge_w = (const float*)d_in[4];
    const float* ln1_w   = (const float*)d_in[5];
    const float* ln1_b   = (const float*)d_in[6];
    const float* ln2_w   = (const float*)d_in[7];
    const float* ln2_b   = (const float*)d_in[8];
    const float* fc1_w   = (const float*)d_in[9];
    const float* fc1_b   = (const float*)d_in[10];
    const float* fc2_w   = (const float*)d_in[11];
    const float* fc2_b   = (const float*)d_in[12];
    const float* gamma   = (const float*)d_in[13];
    float* out = (float*)d_out;

    float *n_, *qk_, *v_, *m_, *xm_, *h1_, *h2_;
    cudaGetSymbolAddress((void**)&n_,   g_n);
    cudaGetSymbolAddress((void**)&qk_,  g_qk);
    cudaGetSymbolAddress((void**)&v_,   g_v);
    cudaGetSymbolAddress((void**)&m_,   g_m);
    cudaGetSymbolAddress((void**)&xm_,  g_xm);
    cudaGetSymbolAddress((void**)&h1_,  g_h1);
    cudaGetSymbolAddress((void**)&h2_,  g_h2);

    // 1. LayerNorm both streams
    ln1_kernel<<<TTOK / 8, 256>>>(x0, x1, ln1_w, ln1_b, n_);

    // 2. qk & v projections (fp32 SIMT f32x2, qk fused with scale 32^-0.25)
    dim3 gproj(CDIM / 64, TTOK / 64);
    gemm_kernel<<<gproj, 256>>>(n_, CDIM, qk_w, qk_, CDIM, CDIM, QK_SCALE);
    gemm_kernel<<<gproj, 256>>>(n_, CDIM, v_w,  v_,  CDIM, CDIM, 1.0f);

    // 3. tensor-core dual-direction flash attention (32 rows/warp, paired layouts)
    attn_tc_kernel<<<dim3(SEQ / 128, HEADS, 4), 128>>>(qk_, v_, m_);

    // 4. build concat buffer: cols [0,256) = x, cols [256,512) = m @ merge_w^T (tf32)
    copyx_kernel<<<(TTOK * CDIM / 4 + 255) / 256, 256>>>(x0, x1, xm_);
    gemm_tf32<<<dim3(CDIM / 64, TTOK / 128), 256>>>(m_, CDIM, merge_w, nullptr, xm_ + CDIM, 2 * CDIM, CDIM, 0);

    // 5. fc1 + exact GELU (tf32)
    gemm_tf32<<<dim3(HID / 64, TTOK / 128), 256>>>(xm_, 2 * CDIM, fc1_w, fc1_b, h1_, HID, 2 * CDIM, 1);

    // 6. fc2 (tf32)
    gemm_tf32<<<dim3(CDIM / 64, TTOK / 128), 256>>>(h1_, HID, fc2_w, fc2_b, h2_, CDIM, HID, 0);

    // 7. residual + LN2 epilogue -> output
    final_kernel<<<TTOK / 8, 256>>>(x0, x1, h2_, gamma, ln2_w, ln2_b, out);
}

// round 15
// speedup vs baseline: 1.0300x; 1.0300x over previous
#include <cuda_runtime.h>
#include <math.h>
#include <stdint.h>

// Problem constants
#define BATCH 2
#define SEQ   2048
#define CDIM  256
#define HEADS 8
#define HDIM  32
#define TOK   4096          // tokens per stream (BATCH*SEQ)
#define TTOK  8192          // total tokens (both streams)
#define HID   1024

// qk scale: 32^-0.25 (applied to both sides in reference)
#define QK_SCALE 0.42044820762685725f

// ---------------- scratch (static device allocations) ----------------
__device__ float g_n [TTOK * CDIM];        // ln1 output
__device__ float g_qk[TTOK * CDIM];        // qk projection (scaled)
__device__ float g_v [TTOK * CDIM];        // v projection
__device__ float g_m [TTOK * CDIM];        // attention output
__device__ float g_xm[TTOK * 2 * CDIM];    // concat(x, m@merge_w^T), ld=512
__device__ float g_h1[TTOK * HID];         // fc1+gelu output
__device__ float g_h2[TTOK * CDIM];        // fc2 output

// ---------------- packed f32x2 helpers ----------------
typedef unsigned long long u64;
__device__ __forceinline__ u64 f2fma(u64 a, u64 b, u64 c) {
    u64 d; asm("fma.rn.f32x2 %0, %1, %2, %3;" : "=l"(d) : "l"(a), "l"(b), "l"(c)); return d;
}
__device__ __forceinline__ u64 f2mul(u64 a, u64 b) {
    u64 d; asm("mul.rn.f32x2 %0, %1, %2;" : "=l"(d) : "l"(a), "l"(b)); return d;
}
__device__ __forceinline__ u64 f2pack(float x) {
    u64 d; asm("mov.b64 %0, {%1, %1};" : "=l"(d) : "f"(x)); return d;
}
__device__ __forceinline__ float f2lo(u64 a) {
    float lo, hi; asm("mov.b64 {%0, %1}, %2;" : "=f"(lo), "=f"(hi) : "l"(a)); return lo;
}
__device__ __forceinline__ float f2hi(u64 a) {
    float lo, hi; asm("mov.b64 {%0, %1}, %2;" : "=f"(lo), "=f"(hi) : "l"(a)); return hi;
}

// ---------------- LayerNorm (warp per token) ----------------
__global__ void ln1_kernel(const float* __restrict__ x0, const float* __restrict__ x1,
                           const float* __restrict__ w, const float* __restrict__ b,
                           float* __restrict__ out)
{
    int gwarp = (blockIdx.x * blockDim.x + threadIdx.x) >> 5;
    int lane = threadIdx.x & 31;
    if (gwarp >= TTOK) return;
    const float* x = (gwarp < TOK) ? (x0 + (size_t)gwarp * CDIM)
                                   : (x1 + (size_t)(gwarp - TOK) * CDIM);
    float4 a = ((const float4*)x)[lane];
    float4 c = ((const float4*)x)[lane + 32];
    float sum = a.x + a.y + a.z + a.w + c.x + c.y + c.z + c.w;
    float sq  = a.x*a.x + a.y*a.y + a.z*a.z + a.w*a.w
              + c.x*c.x + c.y*c.y + c.z*c.z + c.w*c.w;
    #pragma unroll
    for (int o = 16; o; o >>= 1) {
        sum += __shfl_xor_sync(0xffffffffu, sum, o);
        sq  += __shfl_xor_sync(0xffffffffu, sq,  o);
    }
    float mean = sum * (1.0f / CDIM);
    float var  = sq * (1.0f / CDIM) - mean * mean;
    float rstd = rsqrtf(var + 1e-5f);

    float4 w0 = ((const float4*)w)[lane];
    float4 w1 = ((const float4*)w)[lane + 32];
    float4 b0 = ((const float4*)b)[lane];
    float4 b1 = ((const float4*)b)[lane + 32];
    float4 o0, o1;
    o0.x = (a.x - mean) * rstd * w0.x + b0.x;
    o0.y = (a.y - mean) * rstd * w0.y + b0.y;
    o0.z = (a.z - mean) * rstd * w0.z + b0.z;
    o0.w = (a.w - mean) * rstd * w0.w + b0.w;
    o1.x = (c.x - mean) * rstd * w1.x + b1.x;
    o1.y = (c.y - mean) * rstd * w1.y + b1.y;
    o1.z = (c.z - mean) * rstd * w1.z + b1.z;
    o1.w = (c.w - mean) * rstd * w1.w + b1.w;
    float4* op = (float4*)(out + (size_t)gwarp * CDIM);
    op[lane] = o0;
    op[lane + 32] = o1;
}

__device__ __forceinline__ float gelu_exact(float x) {
    return 0.5f * x * (1.0f + erff(x * 0.70710678118654752f));
}

// ---------------- fp32 SIMT GEMM w/ packed f32x2 (qk/v projections) ----------------
__global__ void gemm_kernel(const float* __restrict__ A, int lda,
                            const float* __restrict__ W,
                            float* __restrict__ Cc, int ldc,
                            int K, float scale)
{
    __shared__ float As[16][68];
    __shared__ float Bs[16][68];

    int tid = threadIdx.x;                 // 256 threads
    int m0 = blockIdx.y * 64;
    int n0 = blockIdx.x * 64;
    int lrow = tid >> 2;                   // 0..63
    int lk   = (tid & 3) << 2;             // 0,4,8,12
    const float* Aptr = A + (size_t)(m0 + lrow) * lda + lk;
    const float* Wptr = W + (size_t)(n0 + lrow) * K + lk;

    int ty = tid >> 4;
    int tx = tid & 15;

    u64 acc2[4][2];
    #pragma unroll
    for (int i = 0; i < 4; i++) { acc2[i][0] = 0ull; acc2[i][1] = 0ull; }

    for (int k0 = 0; k0 < K; k0 += 16) {
        float4 av = *(const float4*)(Aptr + k0);
        float4 wv = *(const float4*)(Wptr + k0);
        As[lk + 0][lrow] = av.x; As[lk + 1][lrow] = av.y;
        As[lk + 2][lrow] = av.z; As[lk + 3][lrow] = av.w;
        Bs[lk + 0][lrow] = wv.x; Bs[lk + 1][lrow] = wv.y;
        Bs[lk + 2][lrow] = wv.z; Bs[lk + 3][lrow] = wv.w;
        __syncthreads();
        #pragma unroll
        for (int kk = 0; kk < 16; kk++) {
            float4 a4 = *(const float4*)&As[kk][ty * 4];
            const u64* bp = (const u64*)&Bs[kk][tx * 4];
            u64 b0 = bp[0], b1 = bp[1];
            u64 a0 = f2pack(a4.x), a1 = f2pack(a4.y);
            u64 a2 = f2pack(a4.z), a3 = f2pack(a4.w);
            acc2[0][0] = f2fma(a0, b0, acc2[0][0]);
            acc2[0][1] = f2fma(a0, b1, acc2[0][1]);
            acc2[1][0] = f2fma(a1, b0, acc2[1][0]);
            acc2[1][1] = f2fma(a1, b1, acc2[1][1]);
            acc2[2][0] = f2fma(a2, b0, acc2[2][0]);
            acc2[2][1] = f2fma(a2, b1, acc2[2][1]);
            acc2[3][0] = f2fma(a3, b0, acc2[3][0]);
            acc2[3][1] = f2fma(a3, b1, acc2[3][1]);
        }
        __syncthreads();
    }

    u64 sp = f2pack(scale);
    #pragma unroll
    for (int i = 0; i < 4; i++) {
        int row = m0 + ty * 4 + i;
        u64 v0 = f2mul(acc2[i][0], sp);
        u64 v1 = f2mul(acc2[i][1], sp);
        float4 o;
        o.x = f2lo(v0); o.y = f2hi(v0);
        o.z = f2lo(v1); o.w = f2hi(v1);
        *(float4*)&Cc[(size_t)row * ldc + n0 + tx * 4] = o;
    }
}

// ---------------- tf32 helpers ----------------
__device__ __forceinline__ float to_tf32(float x) {
    uint32_t u; asm("cvt.rna.tf32.f32 %0, %1;" : "=r"(u) : "f"(x));
    return __uint_as_float(u);
}

__device__ __forceinline__ void mma_tf32(float* c, const float* a, const float* b) {
    asm volatile(
        "mma.sync.aligned.m16n8k8.row.col.f32.tf32.tf32.f32 "
        "{%0,%1,%2,%3}, {%4,%5,%6,%7}, {%8,%9}, {%0,%1,%2,%3};"
        : "+f"(c[0]), "+f"(c[1]), "+f"(c[2]), "+f"(c[3])
        : "r"(__float_as_uint(a[0])), "r"(__float_as_uint(a[1])),
          "r"(__float_as_uint(a[2])), "r"(__float_as_uint(a[3])),
          "r"(__float_as_uint(b[0])), "r"(__float_as_uint(b[1])));
}

// ---------------- tf32 tensor-core GEMM: C = act(A @ W^T + bias) ----------------
__global__ __launch_bounds__(256) void gemm_tf32(
    const float* __restrict__ A, int lda,
    const float* __restrict__ W,
    const float* __restrict__ bias,
    float* __restrict__ Cc, int ldc,
    int K, int act)
{
    __shared__ float As[128][36];
    __shared__ float Ws[64][36];

    int tid = threadIdx.x;
    int lane = tid & 31;
    int warp = tid >> 5;          // 0..7
    int warp_m = warp & 3;
    int warp_n = warp >> 2;
    int m0 = blockIdx.y * 128;
    int n0 = blockIdx.x * 64;

    int grp = lane >> 2;          // 0..7
    int tig = lane & 3;           // 0..3

    float acc[2][4][4];
    #pragma unroll
    for (int mt = 0; mt < 2; mt++)
        #pragma unroll
        for (int nt = 0; nt < 4; nt++)
            #pragma unroll
            for (int r = 0; r < 4; r++) acc[mt][nt][r] = 0.0f;

    for (int k0 = 0; k0 < K; k0 += 32) {
        #pragma unroll
        for (int i = 0; i < 4; i++) {
            int idx = tid + i * 256;
            int row = idx >> 3;
            int kc  = (idx & 7) << 2;
            float4 v = *(const float4*)&A[(size_t)(m0 + row) * lda + k0 + kc];
            As[row][kc + 0] = to_tf32(v.x);
            As[row][kc + 1] = to_tf32(v.y);
            As[row][kc + 2] = to_tf32(v.z);
            As[row][kc + 3] = to_tf32(v.w);
        }
        #pragma unroll
        for (int i = 0; i < 2; i++) {
            int idx = tid + i * 256;
            int row = idx >> 3;
            int kc  = (idx & 7) << 2;
            float4 v = *(const float4*)&W[(size_t)(n0 + row) * K + k0 + kc];
            Ws[row][kc + 0] = to_tf32(v.x);
            Ws[row][kc + 1] = to_tf32(v.y);
            Ws[row][kc + 2] = to_tf32(v.z);
            Ws[row][kc + 3] = to_tf32(v.w);
        }
        __syncthreads();

        #pragma unroll
        for (int ks = 0; ks < 4; ks++) {
            int kb = ks * 8;
            float a[2][4];
            #pragma unroll
            for (int mt = 0; mt < 2; mt++) {
                int rb = warp_m * 32 + mt * 16;
                a[mt][0] = As[rb + grp    ][kb + tig];
                a[mt][1] = As[rb + grp + 8][kb + tig];
                a[mt][2] = As[rb + grp    ][kb + tig + 4];
                a[mt][3] = As[rb + grp + 8][kb + tig + 4];
            }
            float b[4][2];
            #pragma unroll
            for (int nt = 0; nt < 4; nt++) {
                int nb = warp_n * 32 + nt * 8 + grp;
                b[nt][0] = Ws[nb][kb + tig];
                b[nt][1] = Ws[nb][kb + tig + 4];
            }
            #pragma unroll
            for (int mt = 0; mt < 2; mt++)
                #pragma unroll
                for (int nt = 0; nt < 4; nt++)
                    mma_tf32(acc[mt][nt], a[mt], b[nt]);
        }
        __syncthreads();
    }

    #pragma unroll
    for (int mt = 0; mt < 2; mt++) {
        #pragma unroll
        for (int nt = 0; nt < 4; nt++) {
            int r = m0 + warp_m * 32 + mt * 16 + grp;
            int c = n0 + warp_n * 32 + nt * 8 + tig * 2;
            float b0 = bias ? bias[c]     : 0.0f;
            float b1 = bias ? bias[c + 1] : 0.0f;
            float v0 = acc[mt][nt][0] + b0;
            float v1 = acc[mt][nt][1] + b1;
            float v2 = acc[mt][nt][2] + b0;
            float v3 = acc[mt][nt][3] + b1;
            if (act) { v0 = gelu_exact(v0); v1 = gelu_exact(v1);
                       v2 = gelu_exact(v2); v3 = gelu_exact(v3); }
            float2 p0 = make_float2(v0, v1);
            float2 p1 = make_float2(v2, v3);
            *(float2*)&Cc[(size_t)r * ldc + c]       = p0;
            *(float2*)&Cc[(size_t)(r + 8) * ldc + c] = p1;
        }
    }
}

// ---------------- tensor-core dual-direction flash attention (v3) ----------------
// R9 parallelism (64 q-rows/block, 16/warp, grid 1024) + R10 paired SMEM layouts
// (B-fragments = one LDS.64, P A-fragments = one LDS.128).
__global__ __launch_bounds__(128, 4)
void attn_tc_kernel(const float* __restrict__ qk, const float* __restrict__ v,
                    float* __restrict__ out)
{
    // Kp[ks][tig][key] = {K[key][8ks+tig], K[key][8ks+tig+4]}  (key pad 68)
    __shared__ float2 Kp[4][4][68];
    // Vp[ks][tig][dim] = {V[8ks+tig][dim], V[8ks+tig+4][dim]}  (dim pad 36)
    __shared__ float2 Vp[8][4][36];
    // Pq[warp][ks][tig][grp] = A-fragment float4 (grp pad 10)
    __shared__ float4 Pq[4][8][4][10];

    const int combo = blockIdx.z;
    const int dir = combo >> 1, bb = combo & 1;
    const int h = blockIdx.y;
    const int q_base = dir * TOK + bb * SEQ;
    const int k_base = (dir ^ 1) * TOK + bb * SEQ;
    const int tid = threadIdx.x;
    const int warp = tid >> 5, lane = tid & 31;
    const int grp = lane >> 2, tig = lane & 3;
    const int m0 = blockIdx.x * 64 + warp * 16;

    // Q fragment (single m-tile per warp)
    float qa[4][4];
    {
        const float* qr0 = &qk[(size_t)(q_base + m0 + grp) * CDIM + h * HDIM];
        const float* qr1 = &qk[(size_t)(q_base + m0 + grp + 8) * CDIM + h * HDIM];
        #pragma unroll
        for (int s = 0; s < 4; s++) {
            qa[s][0] = to_tf32(qr0[8 * s + tig]);
            qa[s][1] = to_tf32(qr1[8 * s + tig]);
            qa[s][2] = to_tf32(qr0[8 * s + tig + 4]);
            qa[s][3] = to_tf32(qr1[8 * s + tig + 4]);
        }
    }

    float o[4][4];
    #pragma unroll
    for (int nt = 0; nt < 4; nt++)
        #pragma unroll
        for (int r = 0; r < 4; r++) o[nt][r] = 0.0f;
    float m_lo = -1e30f, m_hi = -1e30f, l_lo = 0.0f, l_hi = 0.0f;

    for (int kt = 0; kt < SEQ; kt += 64) {
        // ---- load K/V tile into paired layouts ----
        #pragma unroll
        for (int i = 0; i < 4; i++) {
            int idx = tid + i * 128;          // 512 float4 slots
            int key = idx >> 3;
            int c4  = (idx & 7) << 2;         // dims c4..c4+3
            size_t goff = (size_t)(k_base + kt + key) * CDIM + h * HDIM + c4;
            float4 kv = *(const float4*)&qk[goff];
            int ksk = c4 >> 3;
            if ((c4 & 4) == 0) {
                Kp[ksk][0][key].x = to_tf32(kv.x);
                Kp[ksk][1][key].x = to_tf32(kv.y);
                Kp[ksk][2][key].x = to_tf32(kv.z);
                Kp[ksk][3][key].x = to_tf32(kv.w);
            } else {
                Kp[ksk][0][key].y = to_tf32(kv.x);
                Kp[ksk][1][key].y = to_tf32(kv.y);
                Kp[ksk][2][key].y = to_tf32(kv.z);
                Kp[ksk][3][key].y = to_tf32(kv.w);
            }
            float4 vv = *(const float4*)&v[goff];
            int ksv = key >> 3;
            int rv = key & 7;
            int tv = rv & 3;
            if (rv < 4) {
                Vp[ksv][tv][c4 + 0].x = to_tf32(vv.x);
                Vp[ksv][tv][c4 + 1].x = to_tf32(vv.y);
                Vp[ksv][tv][c4 + 2].x = to_tf32(vv.z);
                Vp[ksv][tv][c4 + 3].x = to_tf32(vv.w);
            } else {
                Vp[ksv][tv][c4 + 0].y = to_tf32(vv.x);
                Vp[ksv][tv][c4 + 1].y = to_tf32(vv.y);
                Vp[ksv][tv][c4 + 2].y = to_tf32(vv.z);
                Vp[ksv][tv][c4 + 3].y = to_tf32(vv.w);
            }
        }
        __syncthreads();

        // ---- S = Q @ K^T ----
        float s[8][4];
        #pragma unroll
        for (int nt = 0; nt < 8; nt++)
            #pragma unroll
            for (int r = 0; r < 4; r++) s[nt][r] = 0.0f;
        #pragma unroll
        for (int ks = 0; ks < 4; ks++) {
            #pragma unroll
            for (int nt = 0; nt < 8; nt++) {
                float2 kb = Kp[ks][tig][nt * 8 + grp];
                float bfr[2] = {kb.x, kb.y};
                mma_tf32(s[nt], qa[ks], bfr);
            }
        }

        // ---- online softmax (rows grp / grp+8) ----
        float mx_lo = -1e30f, mx_hi = -1e30f;
        #pragma unroll
        for (int nt = 0; nt < 8; nt++) {
            mx_lo = fmaxf(mx_lo, fmaxf(s[nt][0], s[nt][1]));
            mx_hi = fmaxf(mx_hi, fmaxf(s[nt][2], s[nt][3]));
        }
        mx_lo = fmaxf(mx_lo, __shfl_xor_sync(0xffffffffu, mx_lo, 1));
        mx_lo = fmaxf(mx_lo, __shfl_xor_sync(0xffffffffu, mx_lo, 2));
        mx_hi = fmaxf(mx_hi, __shfl_xor_sync(0xffffffffu, mx_hi, 1));
        mx_hi = fmaxf(mx_hi, __shfl_xor_sync(0xffffffffu, mx_hi, 2));

        float mn_lo = fmaxf(m_lo, mx_lo);
        float mn_hi = fmaxf(m_hi, mx_hi);
        float corr_lo = __expf(m_lo - mn_lo);
        float corr_hi = __expf(m_hi - mn_hi);
        m_lo = mn_lo; m_hi = mn_hi;
        l_lo *= corr_lo; l_hi *= corr_hi;
        #pragma unroll
        for (int nt = 0; nt < 4; nt++) {
            o[nt][0] *= corr_lo; o[nt][1] *= corr_lo;
            o[nt][2] *= corr_hi; o[nt][3] *= corr_hi;
        }

        float sum_lo = 0.0f, sum_hi = 0.0f;
        #pragma unroll
        for (int nt = 0; nt < 8; nt++) {
            s[nt][0] = __expf(s[nt][0] - mn_lo);
            s[nt][1] = __expf(s[nt][1] - mn_lo);
            s[nt][2] = __expf(s[nt][2] - mn_hi);
            s[nt][3] = __expf(s[nt][3] - mn_hi);
            sum_lo += s[nt][0] + s[nt][1];
            sum_hi += s[nt][2] + s[nt][3];
        }
        sum_lo += __shfl_xor_sync(0xffffffffu, sum_lo, 1);
        sum_lo += __shfl_xor_sync(0xffffffffu, sum_lo, 2);
        sum_hi += __shfl_xor_sync(0xffffffffu, sum_hi, 1);
        sum_hi += __shfl_xor_sync(0xffffffffu, sum_hi, 2);
        l_lo += sum_lo; l_hi += sum_hi;

        // ---- stage P as A-fragments: two STS.64 per n-tile ----
        {
            int tp  = (2 * tig) & 3;
            int off = (tig < 2) ? 0 : 2;
            #pragma unroll
            for (int nt = 0; nt < 8; nt++) {
                float* b0 = (float*)&Pq[warp][nt][tp][grp] + off;
                float* b1 = (float*)&Pq[warp][nt][tp + 1][grp] + off;
                *(float2*)b0 = make_float2(to_tf32(s[nt][0]), to_tf32(s[nt][2]));
                *(float2*)b1 = make_float2(to_tf32(s[nt][1]), to_tf32(s[nt][3]));
            }
        }
        __syncwarp();

        // ---- O += P @ V : A = one LDS.128, B = one LDS.64 ----
        #pragma unroll
        for (int ks = 0; ks < 8; ks++) {
            float4 af = Pq[warp][ks][tig][grp];
            float a[4] = {af.x, af.y, af.z, af.w};
            #pragma unroll
            for (int nt = 0; nt < 4; nt++) {
                float2 vb = Vp[ks][tig][nt * 8 + grp];
                float bfr[2] = {vb.x, vb.y};
                mma_tf32(o[nt], a, bfr);
            }
        }
        __syncthreads();
    }

    // ---- normalize & write ----
    float inv_lo = 1.0f / l_lo;
    float inv_hi = 1.0f / l_hi;
    float* or0 = &out[(size_t)(q_base + m0 + grp) * CDIM + h * HDIM];
    float* or1 = &out[(size_t)(q_base + m0 + grp + 8) * CDIM + h * HDIM];
    #pragma unroll
    for (int nt = 0; nt < 4; nt++) {
        *(float2*)&or0[nt * 8 + 2 * tig] = make_float2(o[nt][0] * inv_lo, o[nt][1] * inv_lo);
        *(float2*)&or1[nt * 8 + 2 * tig] = make_float2(o[nt][2] * inv_hi, o[nt][3] * inv_hi);
    }
}

// ---------------- copy x into concat buffer (cols 0..255 of g_xm, ld=512) ----------------
__global__ void copyx_kernel(const float* __restrict__ x0, const float* __restrict__ x1,
                             float* __restrict__ xm)
{
    int idx = blockIdx.x * blockDim.x + threadIdx.x;
    if (idx >= TTOK * CDIM / 4) return;
    int tok = idx >> 6;
    int c4  = idx & 63;
    const float4* src = (const float4*)((tok < TOK) ? (x0 + (size_t)tok * CDIM)
                                                    : (x1 + (size_t)(tok - TOK) * CDIM));
    ((float4*)(xm + (size_t)tok * (2 * CDIM)))[c4] = src[c4];
}

// ---------------- final: out = x + gamma * LN(h2; ln2_w, ln2_b) ----------------
__global__ void final_kernel(const float* __restrict__ x0, const float* __restrict__ x1,
                             const float* __restrict__ h2, const float* __restrict__ gamma,
                             const float* __restrict__ w, const float* __restrict__ b,
                             float* __restrict__ out)
{
    int gwarp = (blockIdx.x * blockDim.x + threadIdx.x) >> 5;
    int lane = threadIdx.x & 31;
    if (gwarp >= TTOK) return;
    const float* x = (gwarp < TOK) ? (x0 + (size_t)gwarp * CDIM)
                                   : (x1 + (size_t)(gwarp - TOK) * CDIM);
    const float* hh = h2 + (size_t)gwarp * CDIM;

    float4 a = ((const float4*)hh)[lane];
    float4 c = ((const float4*)hh)[lane + 32];
    float sum = a.x + a.y + a.z + a.w + c.x + c.y + c.z + c.w;
    float sq  = a.x*a.x + a.y*a.y + a.z*a.z + a.w*a.w
              + c.x*c.x + c.y*c.y + c.z*c.z + c.w*c.w;
    #pragma unroll
    for (int o = 16; o; o >>= 1) {
        sum += __shfl_xor_sync(0xffffffffu, sum, o);
        sq  += __shfl_xor_sync(0xffffffffu, sq,  o);
    }
    float mean = sum * (1.0f / CDIM);
    float var  = sq * (1.0f / CDIM) - mean * mean;
    float rstd = rsqrtf(var + 1e-5f);

    float4 xa = ((const float4*)x)[lane];
    float4 xc = ((const float4*)x)[lane + 32];
    float4 w0 = ((const float4*)w)[lane];
    float4 w1 = ((const float4*)w)[lane + 32];
    float4 b0 = ((const float4*)b)[lane];
    float4 b1 = ((const float4*)b)[lane + 32];
    float4 g0 = ((const float4*)gamma)[lane];
    float4 g1 = ((const float4*)gamma)[lane + 32];

    float4 o0, o1;
    o0.x = xa.x + g0.x * ((a.x - mean) * rstd * w0.x + b0.x);
    o0.y = xa.y + g0.y * ((a.y - mean) * rstd * w0.y + b0.y);
    o0.z = xa.z + g0.z * ((a.z - mean) * rstd * w0.z + b0.z);
    o0.w = xa.w + g0.w * ((a.w - mean) * rstd * w0.w + b0.w);
    o1.x = xc.x + g1.x * ((c.x - mean) * rstd * w1.x + b1.x);
    o1.y = xc.y + g1.y * ((c.y - mean) * rstd * w1.y + b1.y);
    o1.z = xc.z + g1.z * ((c.z - mean) * rstd * w1.z + b1.z);
    o1.w = xc.w + g1.w * ((c.w - mean) * rstd * w1.w + b1.w);

    float4* op = (float4*)(out + (size_t)gwarp * CDIM);
    op[lane] = o0;
    op[lane + 32] = o1;
}

// ---------------- launch ----------------
extern "C" void kernel_launch(void* const* d_in, const int* in_sizes, int n_in,
                              void* d_out, int out_size)
{
    const float* x0      = (const float*)d_in[0];
    const float* x1      = (const float*)d_in[1];
    const float* qk_w    = (const float*)d_in[2];
    const float* v_w     = (const float*)d_in[3];
    const float* merge_w = (const float*)d_in[4];
    const float* ln1_w   = (const float*)d_in[5];
    const float* ln1_b   = (const float*)d_in[6];
    const float* ln2_w   = (const float*)d_in[7];
    const float* ln2_b   = (const float*)d_in[8];
    const float* fc1_w   = (const float*)d_in[9];
    const float* fc1_b   = (const float*)d_in[10];
    const float* fc2_w   = (const float*)d_in[11];
    const float* fc2_b   = (const float*)d_in[12];
    const float* gamma   = (const float*)d_in[13];
    float* out = (float*)d_out;

    float *n_, *qk_, *v_, *m_, *xm_, *h1_, *h2_;
    cudaGetSymbolAddress((void**)&n_,   g_n);
    cudaGetSymbolAddress((void**)&qk_,  g_qk);
    cudaGetSymbolAddress((void**)&v_,   g_v);
    cudaGetSymbolAddress((void**)&m_,   g_m);
    cudaGetSymbolAddress((void**)&xm_,  g_xm);
    cudaGetSymbolAddress((void**)&h1_,  g_h1);
    cudaGetSymbolAddress((void**)&h2_,  g_h2);

    // 1. LayerNorm both streams
    ln1_kernel<<<TTOK / 8, 256>>>(x0, x1, ln1_w, ln1_b, n_);

    // 2. qk & v projections (fp32 SIMT f32x2, qk fused with scale 32^-0.25)
    dim3 gproj(CDIM / 64, TTOK / 64);
    gemm_kernel<<<gproj, 256>>>(n_, CDIM, qk_w, qk_, CDIM, CDIM, QK_SCALE);
    gemm_kernel<<<gproj, 256>>>(n_, CDIM, v_w,  v_,  CDIM, CDIM, 1.0f);

    // 3. tensor-core dual-direction flash attention (16 rows/warp, paired layouts, grid 1024)
    attn_tc_kernel<<<dim3(SEQ / 64, HEADS, 4), 128>>>(qk_, v_, m_);

    // 4. build concat buffer: cols [0,256) = x, cols [256,512) = m @ merge_w^T (tf32)
    copyx_kernel<<<(TTOK * CDIM / 4 + 255) / 256, 256>>>(x0, x1, xm_);
    gemm_tf32<<<dim3(CDIM / 64, TTOK / 128), 256>>>(m_, CDIM, merge_w, nullptr, xm_ + CDIM, 2 * CDIM, CDIM, 0);

    // 5. fc1 + exact GELU (tf32)
    gemm_tf32<<<dim3(HID / 64, TTOK / 128), 256>>>(xm_, 2 * CDIM, fc1_w, fc1_b, h1_, HID, 2 * CDIM, 1);

    // 6. fc2 (tf32)
    gemm_tf32<<<dim3(CDIM / 64, TTOK / 128), 256>>>(h1_, HID, fc2_w, fc2_b, h2_, CDIM, HID, 0);

    // 7. residual + LN2 epilogue -> output
    final_kernel<<<TTOK / 8, 256>>>(x0, x1, h2_, gamma, ln2_w, ln2_b, out);
}